// round 1
// baseline (speedup 1.0000x reference)
#include <cuda_runtime.h>
#include <cuda_bf16.h>
#include <stdint.h>

#define BROWS 256
#define DDIM  1024
#define HDIM  2048
#define NOUT  2048   // 2*D

// ---------------- scratch (__device__ globals; no allocation allowed) ----------
__device__ float          g_mu[BROWS * DDIM];
__device__ __nv_bfloat16  g_mubf[BROWS * DDIM];
__device__ __nv_bfloat16  g_w1bf[DDIM * HDIM];
__device__ __nv_bfloat16  g_w2bf[HDIM * NOUT];
__device__ __nv_bfloat16  g_h[BROWS * HDIM];
__device__ float          g_out[BROWS * NOUT];
__device__ float g_c1[BROWS], g_c2[BROWS], g_invg[BROWS], g_r[BROWS], g_wgt[BROWS];
__device__ int   g_lowt[BROWS];
__device__ float g_partial[BROWS];

// ---------------- per-row scalars ----------------------------------------------
// gamma = 1 - 0.02^(2t); 0.02^(2t) = exp(2t * ln(0.02)); ln(0.02) = -3.912023005428146
__global__ void row_scalars_k(const float* __restrict__ t) {
    int b = threadIdx.x;
    float tv = t[b];
    float sg = expf(-7.824046010856292f * tv);   // = 0.02^(2t) = 1 - gamma
    float gamma = 1.0f - sg;
    g_c1[b]   = gamma;
    g_c2[b]   = gamma * sg;          // gamma*(1-gamma)
    g_invg[b] = 1.0f / gamma;
    g_r[b]    = sqrtf(sg / gamma);   // sqrt((1-gamma)/gamma)
    g_wgt[b]  = 1.0f / sg;           // 0.02^(-2t)
    g_lowt[b] = (tv < 1e-10f) ? 1 : 0;
}

// ---------------- mu = gamma*x + gamma*(1-gamma)*noise --------------------------
__global__ void prep_mu_k(const float* __restrict__ x, const float* __restrict__ noise) {
    int i = blockIdx.x * blockDim.x + threadIdx.x;   // i < 262144
    int b = i >> 10;
    float mu = g_c1[b] * x[i] + g_c2[b] * noise[i];
    g_mu[i]   = mu;
    g_mubf[i] = __float2bfloat16(mu);
}

// ---------------- fp32 -> bf16 weight conversion --------------------------------
__global__ void convert_w_k(const float* __restrict__ src, int which, int n4) {
    int i = blockIdx.x * blockDim.x + threadIdx.x;
    if (i >= n4) return;
    __nv_bfloat16* dst = which ? g_w2bf : g_w1bf;
    float4 v = ((const float4*)src)[i];
    ((__nv_bfloat162*)dst)[2 * i]     = __floats2bfloat162_rn(v.x, v.y);
    ((__nv_bfloat162*)dst)[2 * i + 1] = __floats2bfloat162_rn(v.z, v.w);
}

// ---------------- mma.sync m16n8k16 bf16 ---------------------------------------
__device__ __forceinline__ void mma16816(float* c, const uint32_t* a, const uint32_t* b) {
    asm volatile(
        "mma.sync.aligned.m16n8k16.row.col.f32.bf16.bf16.f32 "
        "{%0,%1,%2,%3}, {%4,%5,%6,%7}, {%8,%9}, {%0,%1,%2,%3};\n"
        : "+f"(c[0]), "+f"(c[1]), "+f"(c[2]), "+f"(c[3])
        : "r"(a[0]), "r"(a[1]), "r"(a[2]), "r"(a[3]), "r"(b[0]), "r"(b[1]));
}

// ---------------- GEMM: C(256xN) = A(256xK) @ B(KxN), N = 2048 ------------------
// MODE 1: A = g_mubf (K=1024), B = g_w1bf. Epilogue: + b1 + t*W1last, leaky, -> g_h (bf16)
// MODE 2: A = g_h    (K=2048), B = g_w2bf. Epilogue: + b2                -> g_out (fp32)
#define BM 64
#define BN 64
#define BK 32
#define BKP 40
#define BNP 72

template<int MODE>
__global__ void __launch_bounds__(256) gemm_k(int Kdim,
                                              const float* __restrict__ bias,
                                              const float* __restrict__ tvec,
                                              const float* __restrict__ w1last) {
    __shared__ __nv_bfloat16 As[2][BM * BKP];   // row-major [m][k]
    __shared__ __nv_bfloat16 Bs[2][BK * BNP];   // row-major [k][n]

    const __nv_bfloat16* A  = (MODE == 1) ? g_mubf : g_h;
    const __nv_bfloat16* Bm = (MODE == 1) ? g_w1bf : g_w2bf;

    int tid = threadIdx.x;
    int m0 = blockIdx.y * BM;
    int n0 = blockIdx.x * BN;

    // global-load mapping: one uint4 (8 bf16) per thread per tile, for A and B
    int arow = tid >> 2;             // 0..63
    int acol = (tid & 3) * 8;        // 0..24
    const __nv_bfloat16* Ag = A + (size_t)(m0 + arow) * Kdim + acol;
    int brow = tid >> 3;             // 0..31 (k)
    int bcol = (tid & 7) * 8;        // 0..56 (n)
    const __nv_bfloat16* Bg = Bm + (size_t)brow * 2048 + n0 + bcol;

    int wid = tid >> 5, lane = tid & 31;
    int g = lane >> 2, tc = lane & 3;
    int wm = (wid >> 2) * 32;        // 0 / 32
    int wn = (wid & 3) * 16;         // 0 / 16 / 32 / 48

    float c[2][2][4];
    #pragma unroll
    for (int mf = 0; mf < 2; ++mf)
        #pragma unroll
        for (int nf = 0; nf < 2; ++nf)
            #pragma unroll
            for (int i = 0; i < 4; ++i) c[mf][nf][i] = 0.f;

    uint4 pa = *(const uint4*)Ag;
    uint4 pb = *(const uint4*)Bg;
    *(uint4*)&As[0][arow * BKP + acol] = pa;
    *(uint4*)&Bs[0][brow * BNP + bcol] = pb;
    __syncthreads();

    int ntiles = Kdim / BK;
    for (int tt = 0; tt < ntiles; ++tt) {
        int cur = tt & 1;
        if (tt + 1 < ntiles) {
            pa = *(const uint4*)(Ag + (tt + 1) * BK);
            pb = *(const uint4*)(Bg + (size_t)(tt + 1) * BK * 2048);
        }
        const unsigned short* as = (const unsigned short*)As[cur];
        const unsigned short* bs = (const unsigned short*)Bs[cur];
        #pragma unroll
        for (int kk = 0; kk < BK; kk += 16) {
            uint32_t a[2][4];
            #pragma unroll
            for (int mf = 0; mf < 2; ++mf) {
                int r0 = wm + mf * 16 + g;
                int kb = kk + tc * 2;
                a[mf][0] = *(const uint32_t*)&as[r0 * BKP + kb];
                a[mf][1] = *(const uint32_t*)&as[(r0 + 8) * BKP + kb];
                a[mf][2] = *(const uint32_t*)&as[r0 * BKP + kb + 8];
                a[mf][3] = *(const uint32_t*)&as[(r0 + 8) * BKP + kb + 8];
            }
            uint32_t bf[2][2];
            #pragma unroll
            for (int nf = 0; nf < 2; ++nf) {
                int col = wn + nf * 8 + g;
                int kb = kk + tc * 2;
                uint32_t lo = bs[kb * BNP + col];
                uint32_t hi = bs[(kb + 1) * BNP + col];
                bf[nf][0] = lo | (hi << 16);
                lo = bs[(kb + 8) * BNP + col];
                hi = bs[(kb + 9) * BNP + col];
                bf[nf][1] = lo | (hi << 16);
            }
            #pragma unroll
            for (int mf = 0; mf < 2; ++mf)
                #pragma unroll
                for (int nf = 0; nf < 2; ++nf)
                    mma16816(c[mf][nf], a[mf], bf[nf]);
        }
        if (tt + 1 < ntiles) {
            int nxt = cur ^ 1;
            *(uint4*)&As[nxt][arow * BKP + acol] = pa;
            *(uint4*)&Bs[nxt][brow * BNP + bcol] = pb;
        }
        __syncthreads();
    }

    // epilogue
    #pragma unroll
    for (int mf = 0; mf < 2; ++mf)
        #pragma unroll
        for (int nf = 0; nf < 2; ++nf) {
            int col = n0 + wn + nf * 8 + tc * 2;
            #pragma unroll
            for (int half = 0; half < 2; ++half) {
                int row = m0 + wm + mf * 16 + g + half * 8;
                float v0 = c[mf][nf][half * 2 + 0];
                float v1 = c[mf][nf][half * 2 + 1];
                if (MODE == 1) {
                    float tw = tvec[row];
                    v0 += bias[col]     + tw * w1last[col];
                    v1 += bias[col + 1] + tw * w1last[col + 1];
                    v0 = (v0 >= 0.f) ? v0 : 0.01f * v0;
                    v1 = (v1 >= 0.f) ? v1 : 0.01f * v1;
                    *(__nv_bfloat162*)&g_h[(size_t)row * HDIM + col] =
                        __floats2bfloat162_rn(v0, v1);
                } else {
                    v0 += bias[col];
                    v1 += bias[col + 1];
                    *(float2*)&g_out[(size_t)row * NOUT + col] = make_float2(v0, v1);
                }
            }
        }
}

// ---------------- loss: telescoped discretised CDF + weighted SE ----------------
// pO = (125/128)*G127 - (1/64)*sum_{k=1..126} G_k,  G_k = 0.5*(1+erf((kr_k-mu_x)*inv))
// saturated bins (|arg|>4) contribute exactly 0/1 and are counted analytically.
__global__ void loss_k(const float* __restrict__ x) {
    int b = blockIdx.x;
    int tid = threadIdx.x;
    float invg = g_invg[b], r = g_r[b], w = g_wgt[b];
    int lowt = g_lowt[b];
    float acc = 0.f;
    for (int d = tid; d < DDIM; d += blockDim.x) {
        int idx = b * DDIM + d;
        float me = g_out[b * NOUT + d];
        float ls = g_out[b * NOUT + DDIM + d];
        float mu_x = g_mu[idx] * invg - r * me;
        float sx = r * __expf(ls);
        if (lowt) { mu_x = 0.f; sx = 1.f; }
        float inv  = 0.70710678118654752f / sx;
        float base = (-1.0f - mu_x) * inv;
        float step = 0.015625f * inv;
        // active window: |base + k*step| <= 4  ->  k in center +- 256/inv
        float center = 64.f * (1.f + mu_x);
        float halfw  = 256.f / inv;
        int klo = (int)ceilf(center - halfw);
        int khi = (int)floorf(center + halfw);
        klo = klo < 1 ? 1 : (klo > 127 ? 127 : klo);
        khi = khi < 0 ? 0 : (khi > 126 ? 126 : khi);
        float S = (float)(126 - khi) - (float)(klo - 1);  // saturated erf = +/-1
        for (int k = klo; k <= khi; ++k) {
            S += erff(fmaf((float)k, step, base));
        }
        float G127 = 0.5f + 0.5f * erff(fmaf(127.f, step, base));
        float pO = 0.9765625f * G127 - 0.015625f * (63.f + 0.5f * S);
        float diff = x[idx] - pO;
        acc = fmaf(w * diff, diff, acc);
    }
    __shared__ float red[256];
    red[tid] = acc;
    __syncthreads();
    #pragma unroll
    for (int s = 128; s > 0; s >>= 1) {
        if (tid < s) red[tid] += red[tid + s];
        __syncthreads();
    }
    if (tid == 0) g_partial[b] = red[0];
}

__global__ void finalize_k(float* __restrict__ out) {
    __shared__ double red[256];
    red[threadIdx.x] = (double)g_partial[threadIdx.x];
    __syncthreads();
    #pragma unroll
    for (int s = 128; s > 0; s >>= 1) {
        if (threadIdx.x < s) red[threadIdx.x] += red[threadIdx.x + s];
        __syncthreads();
    }
    // loss = -ln(0.02) * sum / (B*D)
    if (threadIdx.x == 0) out[0] = (float)(3.912023005428146 * red[0] / 262144.0);
}

// ---------------- launch --------------------------------------------------------
extern "C" void kernel_launch(void* const* d_in, const int* in_sizes, int n_in,
                              void* d_out, int out_size) {
    const float* x     = (const float*)d_in[0];   // (256,1024)
    const float* t     = (const float*)d_in[1];   // (256,1)
    const float* noise = (const float*)d_in[2];   // (256,1024)
    const float* W1    = (const float*)d_in[3];   // (1025,2048)
    const float* b1    = (const float*)d_in[4];   // (2048,)
    const float* W2    = (const float*)d_in[5];   // (2048,2048)
    const float* b2    = (const float*)d_in[6];   // (2048,)

    row_scalars_k<<<1, 256>>>(t);
    prep_mu_k<<<(BROWS * DDIM) / 256, 256>>>(x, noise);
    convert_w_k<<<(DDIM * HDIM / 4) / 256, 256>>>(W1, 0, DDIM * HDIM / 4);
    convert_w_k<<<(HDIM * NOUT / 4) / 256, 256>>>(W2, 1, HDIM * NOUT / 4);

    dim3 ggrid(HDIM / BN, BROWS / BM);   // (32, 4)
    gemm_k<1><<<ggrid, 256>>>(DDIM, b1, t, W1 + (size_t)DDIM * HDIM);
    gemm_k<2><<<ggrid, 256>>>(HDIM, b2, nullptr, nullptr);

    loss_k<<<BROWS, 256>>>(x);
    finalize_k<<<1, 256>>>((float*)d_out);
}

// round 4
// speedup vs baseline: 1.5678x; 1.5678x over previous
#include <cuda_runtime.h>
#include <cuda_bf16.h>
#include <stdint.h>

#define BROWS 256
#define DDIM  1024
#define HDIM  2048
#define NOUT  2048   // 2*D

// ---------------- scratch (__device__ globals; no allocation allowed) ----------
__device__ float          g_mu[BROWS * DDIM];
__device__ __nv_bfloat16  g_mubf[BROWS * DDIM];
__device__ __nv_bfloat16  g_w1bf[DDIM * HDIM];   // [k=1024][n=2048]
__device__ __nv_bfloat16  g_w2bf[HDIM * NOUT];   // [k=2048][n=2048]
__device__ __nv_bfloat16  g_h[BROWS * HDIM];
__device__ float          g_out[BROWS * NOUT];
__device__ float g_invg[BROWS], g_r[BROWS], g_wgt[BROWS];
__device__ int   g_lowt[BROWS];
__device__ float g_partial[BROWS];

// ---------------- PTX helpers ----------------------------------------------------
__device__ __forceinline__ uint32_t cvta_shared_u32(const void* p) {
    uint32_t a;
    asm("{ .reg .u64 t; cvta.to.shared.u64 t, %1; cvt.u32.u64 %0, t; }"
        : "=r"(a) : "l"(p));
    return a;
}
__device__ __forceinline__ void cpa16(uint32_t dst, const void* src) {
    asm volatile("cp.async.cg.shared.global [%0], [%1], 16;\n" :: "r"(dst), "l"(src));
}
__device__ __forceinline__ void ldm_x4(uint32_t* r, uint32_t addr) {
    asm volatile("ldmatrix.sync.aligned.m8n8.x4.shared.b16 {%0,%1,%2,%3}, [%4];\n"
                 : "=r"(r[0]), "=r"(r[1]), "=r"(r[2]), "=r"(r[3]) : "r"(addr));
}
__device__ __forceinline__ void ldm_x4t(uint32_t* r, uint32_t addr) {
    asm volatile("ldmatrix.sync.aligned.m8n8.x4.trans.shared.b16 {%0,%1,%2,%3}, [%4];\n"
                 : "=r"(r[0]), "=r"(r[1]), "=r"(r[2]), "=r"(r[3]) : "r"(addr));
}
__device__ __forceinline__ void mma16816(float* c, const uint32_t* a, const uint32_t* b) {
    asm volatile(
        "mma.sync.aligned.m16n8k16.row.col.f32.bf16.bf16.f32 "
        "{%0,%1,%2,%3}, {%4,%5,%6,%7}, {%8,%9}, {%0,%1,%2,%3};\n"
        : "+f"(c[0]), "+f"(c[1]), "+f"(c[2]), "+f"(c[3])
        : "r"(a[0]), "r"(a[1]), "r"(a[2]), "r"(a[3]), "r"(b[0]), "r"(b[1]));
}

// ---------------- prep: mu + per-row loss scalars --------------------------------
// gamma = 1 - 0.02^(2t); ln(0.02) = -3.912023005428146
__global__ void prep_mu_k(const float* __restrict__ x, const float* __restrict__ noise,
                          const float* __restrict__ t) {
    int i = blockIdx.x * blockDim.x + threadIdx.x;   // < 262144
    int b = i >> 10;
    float tv = __ldg(&t[b]);
    float sg = expf(-7.824046010856292f * tv);
    float gamma = 1.0f - sg;
    float mu = gamma * x[i] + gamma * sg * noise[i];
    g_mu[i]   = mu;
    g_mubf[i] = __float2bfloat16(mu);
    if (blockIdx.x == 0 && threadIdx.x < BROWS) {
        int bb = threadIdx.x;
        float tb = t[bb];
        float s2 = expf(-7.824046010856292f * tb);
        float g2 = 1.0f - s2;
        g_invg[bb] = 1.0f / g2;
        g_r[bb]    = sqrtf(s2 / g2);
        g_wgt[bb]  = 1.0f / s2;
        g_lowt[bb] = (tb < 1e-10f) ? 1 : 0;
    }
}

// ---------------- fp32 -> bf16 streaming convert (8 elems/thread) ----------------
// NOTE: destination selected IN DEVICE CODE (which) — passing a __device__ global
// as a host-side kernel argument gives the host shadow address (ATS-silent bug).
__global__ void __launch_bounds__(256) convert_w_k(const float* __restrict__ src,
                                                   int which, int n8) {
    int i = blockIdx.x * blockDim.x + threadIdx.x;
    if (i >= n8) return;
    __nv_bfloat16* dst = which ? g_w2bf : g_w1bf;
    float4 v0 = ((const float4*)src)[2 * i];
    float4 v1 = ((const float4*)src)[2 * i + 1];
    __nv_bfloat162 o[4];
    o[0] = __floats2bfloat162_rn(v0.x, v0.y);
    o[1] = __floats2bfloat162_rn(v0.z, v0.w);
    o[2] = __floats2bfloat162_rn(v1.x, v1.y);
    o[3] = __floats2bfloat162_rn(v1.z, v1.w);
    ((uint4*)dst)[i] = *(uint4*)o;
}

// ---------------- GEMM: C(256 x 2048) = A(256 x K) @ B(K x 2048) -----------------
// MODE 1: A=g_mubf K=1024, B=g_w1bf. Epi: +b1 + t*W1last, leaky -> g_h (bf16)
// MODE 2: A=g_h    K=2048, B=g_w2bf. Epi: +b2 -> g_out (fp32)
// BM=BN=BK=64, 128 threads (4 warps, 2x2, warp tile 32x32), 3-stage cp.async.
#define PITCH_B 144            // padded row pitch in bytes (72 bf16)
#define STAGE_A (64 * PITCH_B)
#define STAGE_BYTES (2 * 64 * PITCH_B)
#define NSTAGE 3

template <int MODE>
__global__ void __launch_bounds__(128) gemm_k(int Kdim,
                                              const float* __restrict__ bias,
                                              const float* __restrict__ tvec,
                                              const float* __restrict__ w1last) {
    extern __shared__ char smem[];
    uint32_t sbase = cvta_shared_u32(smem);

    const __nv_bfloat16* A = (MODE == 1) ? g_mubf : g_h;
    const __nv_bfloat16* B = (MODE == 1) ? g_w1bf : g_w2bf;

    int tid = threadIdx.x, wid = tid >> 5, lane = tid & 31;
    int m0 = blockIdx.y * 64, n0 = blockIdx.x * 64;
    int wm = (wid >> 1) * 32, wn = (wid & 1) * 32;

    float c[2][4][4];
    #pragma unroll
    for (int mf = 0; mf < 2; ++mf)
        #pragma unroll
        for (int nb = 0; nb < 4; ++nb)
            #pragma unroll
            for (int j = 0; j < 4; ++j) c[mf][nb][j] = 0.f;

    int ntiles = Kdim >> 6;

    auto issue = [&](int tt) {
        uint32_t sA = sbase + (uint32_t)(tt % NSTAGE) * STAGE_BYTES;
        uint32_t sB = sA + STAGE_A;
        int k0 = tt << 6;
        #pragma unroll
        for (int i = 0; i < 4; ++i) {
            int id = tid + i * 128;
            int row = id >> 3, c16 = id & 7;
            cpa16(sA + (uint32_t)(row * PITCH_B + c16 * 16),
                  A + (size_t)(m0 + row) * Kdim + k0 + c16 * 8);
        }
        #pragma unroll
        for (int i = 0; i < 4; ++i) {
            int id = tid + i * 128;
            int row = id >> 3, c16 = id & 7;
            cpa16(sB + (uint32_t)(row * PITCH_B + c16 * 16),
                  B + (size_t)(k0 + row) * 2048 + n0 + c16 * 8);
        }
        asm volatile("cp.async.commit_group;\n" ::: "memory");
    };

    issue(0);
    issue(1);

    for (int tt = 0; tt < ntiles; ++tt) {
        asm volatile("cp.async.wait_group 1;\n" ::: "memory");
        __syncthreads();
        if (tt + 2 < ntiles) issue(tt + 2);
        else asm volatile("cp.async.commit_group;\n" ::: "memory");

        uint32_t sA = sbase + (uint32_t)(tt % NSTAGE) * STAGE_BYTES;
        uint32_t sB = sA + STAGE_A;
        #pragma unroll
        for (int ks = 0; ks < 4; ++ks) {
            uint32_t a[2][4], b[2][4];
            #pragma unroll
            for (int mf = 0; mf < 2; ++mf)
                ldm_x4(a[mf], sA + (uint32_t)((wm + mf * 16 + (lane & 15)) * PITCH_B
                                              + (ks * 16 + ((lane >> 4) << 3)) * 2));
            #pragma unroll
            for (int nf = 0; nf < 2; ++nf)
                ldm_x4t(b[nf], sB + (uint32_t)((ks * 16 + (lane & 15)) * PITCH_B
                                               + (wn + nf * 16 + ((lane >> 4) << 3)) * 2));
            #pragma unroll
            for (int mf = 0; mf < 2; ++mf)
                #pragma unroll
                for (int nf = 0; nf < 2; ++nf) {
                    mma16816(c[mf][nf * 2 + 0], a[mf], &b[nf][0]);
                    mma16816(c[mf][nf * 2 + 1], a[mf], &b[nf][2]);
                }
        }
    }

    // epilogue
    int tc = lane & 3, g = lane >> 2;
    #pragma unroll
    for (int mf = 0; mf < 2; ++mf)
        #pragma unroll
        for (int nb = 0; nb < 4; ++nb) {
            int col = n0 + wn + nb * 8 + tc * 2;
            #pragma unroll
            for (int half = 0; half < 2; ++half) {
                int row = m0 + wm + mf * 16 + g + half * 8;
                float v0 = c[mf][nb][half * 2 + 0];
                float v1 = c[mf][nb][half * 2 + 1];
                if (MODE == 1) {
                    float tw = tvec[row];
                    v0 += bias[col]     + tw * w1last[col];
                    v1 += bias[col + 1] + tw * w1last[col + 1];
                    v0 = (v0 >= 0.f) ? v0 : 0.01f * v0;
                    v1 = (v1 >= 0.f) ? v1 : 0.01f * v1;
                    *(__nv_bfloat162*)&g_h[(size_t)row * HDIM + col] =
                        __floats2bfloat162_rn(v0, v1);
                } else {
                    v0 += bias[col];
                    v1 += bias[col + 1];
                    *(float2*)&g_out[(size_t)row * NOUT + col] = make_float2(v0, v1);
                }
            }
        }
}

// ---------------- loss: telescoped discretised CDF + weighted SE ----------------
__global__ void loss_k(const float* __restrict__ x) {
    int b = blockIdx.x;
    int tid = threadIdx.x;
    float invg = g_invg[b], r = g_r[b], w = g_wgt[b];
    int lowt = g_lowt[b];
    float acc = 0.f;
    for (int d = tid; d < DDIM; d += blockDim.x) {
        int idx = b * DDIM + d;
        float me = g_out[b * NOUT + d];
        float ls = g_out[b * NOUT + DDIM + d];
        float mu_x = g_mu[idx] * invg - r * me;
        float sx = r * __expf(ls);
        if (lowt) { mu_x = 0.f; sx = 1.f; }
        float inv  = 0.70710678118654752f / sx;
        float base = (-1.0f - mu_x) * inv;
        float step = 0.015625f * inv;
        float center = 64.f * (1.f + mu_x);
        float halfw  = 256.f / inv;
        int klo = (int)ceilf(center - halfw);
        int khi = (int)floorf(center + halfw);
        klo = klo < 1 ? 1 : (klo > 127 ? 127 : klo);
        khi = khi < 0 ? 0 : (khi > 126 ? 126 : khi);
        float S = (float)(126 - khi) - (float)(klo - 1);
        for (int k = klo; k <= khi; ++k) {
            S += erff(fmaf((float)k, step, base));
        }
        float G127 = 0.5f + 0.5f * erff(fmaf(127.f, step, base));
        float pO = 0.9765625f * G127 - 0.015625f * (63.f + 0.5f * S);
        float diff = x[idx] - pO;
        acc = fmaf(w * diff, diff, acc);
    }
    __shared__ float red[256];
    red[tid] = acc;
    __syncthreads();
    #pragma unroll
    for (int s = 128; s > 0; s >>= 1) {
        if (tid < s) red[tid] += red[tid + s];
        __syncthreads();
    }
    if (tid == 0) g_partial[b] = red[0];
}

__global__ void finalize_k(float* __restrict__ out) {
    __shared__ double red[256];
    red[threadIdx.x] = (double)g_partial[threadIdx.x];
    __syncthreads();
    #pragma unroll
    for (int s = 128; s > 0; s >>= 1) {
        if (threadIdx.x < s) red[threadIdx.x] += red[threadIdx.x + s];
        __syncthreads();
    }
    if (threadIdx.x == 0) out[0] = (float)(3.912023005428146 * red[0] / 262144.0);
}

// ---------------- launch --------------------------------------------------------
extern "C" void kernel_launch(void* const* d_in, const int* in_sizes, int n_in,
                              void* d_out, int out_size) {
    const float* x     = (const float*)d_in[0];   // (256,1024)
    const float* t     = (const float*)d_in[1];   // (256,1)
    const float* noise = (const float*)d_in[2];   // (256,1024)
    const float* W1    = (const float*)d_in[3];   // (1025,2048)
    const float* b1    = (const float*)d_in[4];   // (2048,)
    const float* W2    = (const float*)d_in[5];   // (2048,2048)
    const float* b2    = (const float*)d_in[6];   // (2048,)

    size_t smem = NSTAGE * STAGE_BYTES;   // 55296
    cudaFuncSetAttribute(gemm_k<1>, cudaFuncAttributeMaxDynamicSharedMemorySize, (int)smem);
    cudaFuncSetAttribute(gemm_k<2>, cudaFuncAttributeMaxDynamicSharedMemorySize, (int)smem);

    prep_mu_k<<<(BROWS * DDIM) / 256, 256>>>(x, noise, t);

    convert_w_k<<<(DDIM * HDIM / 8 + 255) / 256, 256>>>(W1, 0, DDIM * HDIM / 8);
    convert_w_k<<<(HDIM * NOUT / 8 + 255) / 256, 256>>>(W2, 1, HDIM * NOUT / 8);

    dim3 ggrid(2048 / 64, BROWS / 64);   // (32, 4) = 128 CTAs
    gemm_k<1><<<ggrid, 128, smem>>>(DDIM, b1, t, W1 + (size_t)DDIM * HDIM);
    gemm_k<2><<<ggrid, 128, smem>>>(HDIM, b2, nullptr, nullptr);

    loss_k<<<BROWS, 256>>>(x);
    finalize_k<<<1, 256>>>((float*)d_out);
}

// round 5
// speedup vs baseline: 1.6509x; 1.0530x over previous
#include <cuda_runtime.h>
#include <cuda_bf16.h>
#include <stdint.h>

#define BROWS 256
#define DDIM  1024
#define HDIM  2048
#define NOUT  2048   // 2*D

// ---------------- scratch (__device__ globals; no allocation allowed) ----------
__device__ float          g_mu[BROWS * DDIM];
__device__ __nv_bfloat16  g_mubf[BROWS * DDIM];
__device__ __nv_bfloat16  g_w1bf[DDIM * HDIM];   // [k=1024][n=2048]
__device__ __nv_bfloat16  g_w2bf[HDIM * NOUT];   // [k=2048][n=2048]
__device__ __nv_bfloat16  g_h[BROWS * HDIM];
__device__ float          g_out[BROWS * NOUT];
__device__ float g_invg[BROWS], g_r[BROWS], g_wgt[BROWS];
__device__ int   g_lowt[BROWS];
__device__ float g_partial[BROWS];

// ---------------- PTX helpers ----------------------------------------------------
__device__ __forceinline__ uint32_t cvta_shared_u32(const void* p) {
    uint32_t a;
    asm("{ .reg .u64 t; cvta.to.shared.u64 t, %1; cvt.u32.u64 %0, t; }"
        : "=r"(a) : "l"(p));
    return a;
}
__device__ __forceinline__ void cpa16(uint32_t dst, const void* src) {
    asm volatile("cp.async.cg.shared.global [%0], [%1], 16;\n" :: "r"(dst), "l"(src));
}
__device__ __forceinline__ void ldm_x4(uint32_t* r, uint32_t addr) {
    asm volatile("ldmatrix.sync.aligned.m8n8.x4.shared.b16 {%0,%1,%2,%3}, [%4];\n"
                 : "=r"(r[0]), "=r"(r[1]), "=r"(r[2]), "=r"(r[3]) : "r"(addr));
}
__device__ __forceinline__ void ldm_x4t(uint32_t* r, uint32_t addr) {
    asm volatile("ldmatrix.sync.aligned.m8n8.x4.trans.shared.b16 {%0,%1,%2,%3}, [%4];\n"
                 : "=r"(r[0]), "=r"(r[1]), "=r"(r[2]), "=r"(r[3]) : "r"(addr));
}
__device__ __forceinline__ void mma16816(float* c, const uint32_t* a, const uint32_t* b) {
    asm volatile(
        "mma.sync.aligned.m16n8k16.row.col.f32.bf16.bf16.f32 "
        "{%0,%1,%2,%3}, {%4,%5,%6,%7}, {%8,%9}, {%0,%1,%2,%3};\n"
        : "+f"(c[0]), "+f"(c[1]), "+f"(c[2]), "+f"(c[3])
        : "r"(a[0]), "r"(a[1]), "r"(a[2]), "r"(a[3]), "r"(b[0]), "r"(b[1]));
}

// ---------------- fused prep: mu + row scalars + both weight converts ------------
// blocks [0,1024): mu, [1024,2048): W1 convert, [2048,4096): W2 convert
__global__ void __launch_bounds__(256) prep_all_k(const float* __restrict__ x,
                                                  const float* __restrict__ noise,
                                                  const float* __restrict__ t,
                                                  const float* __restrict__ W1,
                                                  const float* __restrict__ W2) {
    int blk = blockIdx.x;
    if (blk < 1024) {
        int i = blk * 256 + threadIdx.x;      // < 262144
        int b = i >> 10;
        float tv = __ldg(&t[b]);
        float sg = expf(-7.824046010856292f * tv);
        float gamma = 1.0f - sg;
        float mu = gamma * x[i] + gamma * sg * noise[i];
        g_mu[i]   = mu;
        g_mubf[i] = __float2bfloat16(mu);
        if (blk == 0 && threadIdx.x < BROWS) {
            int bb = threadIdx.x;
            float tb = t[bb];
            float s2 = expf(-7.824046010856292f * tb);
            float g2 = 1.0f - s2;
            g_invg[bb] = 1.0f / g2;
            g_r[bb]    = sqrtf(s2 / g2);
            g_wgt[bb]  = 1.0f / s2;
            g_lowt[bb] = (tb < 1e-10f) ? 1 : 0;
        }
        return;
    }
    const float* src;
    __nv_bfloat16* dst;
    int i;
    if (blk < 2048) {                           // W1: 2M elems -> 256K uint4 stores
        i = (blk - 1024) * 256 + threadIdx.x;
        src = W1; dst = g_w1bf;
    } else {                                    // W2: 4M elems -> 512K uint4 stores
        i = (blk - 2048) * 256 + threadIdx.x;
        src = W2; dst = g_w2bf;
    }
    float4 v0 = ((const float4*)src)[2 * i];
    float4 v1 = ((const float4*)src)[2 * i + 1];
    __nv_bfloat162 o[4];
    o[0] = __floats2bfloat162_rn(v0.x, v0.y);
    o[1] = __floats2bfloat162_rn(v0.z, v0.w);
    o[2] = __floats2bfloat162_rn(v1.x, v1.y);
    o[3] = __floats2bfloat162_rn(v1.z, v1.w);
    ((uint4*)dst)[i] = *(uint4*)o;
}

// ---------------- GEMM: C(256 x 2048) = A(256 x K) @ B(K x 2048) -----------------
// MODE 1: A=g_mubf K=1024, B=g_w1bf. Epi: +b1 + t*W1last, leaky -> g_h (bf16)
// MODE 2: A=g_h    K=2048, B=g_w2bf. Epi: +b2 -> g_out (fp32)
// BM=BN=BK=64, 256 threads (8 warps, 2x4 layout, warp tile 32x16), 3-stage cp.async
#define PITCH_B 144            // padded row pitch in bytes (72 bf16)
#define STAGE_A (64 * PITCH_B)
#define STAGE_BYTES (2 * 64 * PITCH_B)
#define NSTAGE 3

template <int MODE>
__global__ void __launch_bounds__(256) gemm_k(int Kdim,
                                              const float* __restrict__ bias,
                                              const float* __restrict__ tvec,
                                              const float* __restrict__ w1last) {
    extern __shared__ char smem[];
    uint32_t sbase = cvta_shared_u32(smem);

    const __nv_bfloat16* A = (MODE == 1) ? g_mubf : g_h;
    const __nv_bfloat16* B = (MODE == 1) ? g_w1bf : g_w2bf;

    int tid = threadIdx.x, wid = tid >> 5, lane = tid & 31;
    int m0 = blockIdx.y * 64, n0 = blockIdx.x * 64;
    int wm = (wid >> 2) * 32;      // 0 / 32
    int wn = (wid & 3) * 16;       // 0 / 16 / 32 / 48

    float c[2][2][4];              // [mf][n8][4]
    #pragma unroll
    for (int mf = 0; mf < 2; ++mf)
        #pragma unroll
        for (int nb = 0; nb < 2; ++nb)
            #pragma unroll
            for (int j = 0; j < 4; ++j) c[mf][nb][j] = 0.f;

    int ntiles = Kdim >> 6;

    auto issue = [&](int tt) {
        uint32_t sA = sbase + (uint32_t)(tt % NSTAGE) * STAGE_BYTES;
        uint32_t sB = sA + STAGE_A;
        int k0 = tt << 6;
        #pragma unroll
        for (int i = 0; i < 2; ++i) {
            int id = tid + i * 256;           // 0..511
            int row = id >> 3, c16 = id & 7;
            cpa16(sA + (uint32_t)(row * PITCH_B + c16 * 16),
                  A + (size_t)(m0 + row) * Kdim + k0 + c16 * 8);
        }
        #pragma unroll
        for (int i = 0; i < 2; ++i) {
            int id = tid + i * 256;
            int row = id >> 3, c16 = id & 7;
            cpa16(sB + (uint32_t)(row * PITCH_B + c16 * 16),
                  B + (size_t)(k0 + row) * 2048 + n0 + c16 * 8);
        }
        asm volatile("cp.async.commit_group;\n" ::: "memory");
    };

    issue(0);
    issue(1);

    for (int tt = 0; tt < ntiles; ++tt) {
        asm volatile("cp.async.wait_group 1;\n" ::: "memory");
        __syncthreads();
        if (tt + 2 < ntiles) issue(tt + 2);
        else asm volatile("cp.async.commit_group;\n" ::: "memory");

        uint32_t sA = sbase + (uint32_t)(tt % NSTAGE) * STAGE_BYTES;
        uint32_t sB = sA + STAGE_A;
        #pragma unroll
        for (int ks = 0; ks < 4; ++ks) {
            uint32_t a[2][4], b[4];
            #pragma unroll
            for (int mf = 0; mf < 2; ++mf)
                ldm_x4(a[mf], sA + (uint32_t)((wm + mf * 16 + (lane & 15)) * PITCH_B
                                              + (ks * 16 + ((lane >> 4) << 3)) * 2));
            ldm_x4t(b, sB + (uint32_t)((ks * 16 + (lane & 15)) * PITCH_B
                                       + (wn + ((lane >> 4) << 3)) * 2));
            #pragma unroll
            for (int mf = 0; mf < 2; ++mf) {
                mma16816(c[mf][0], a[mf], &b[0]);
                mma16816(c[mf][1], a[mf], &b[2]);
            }
        }
    }

    // epilogue
    int tc = lane & 3, g = lane >> 2;
    #pragma unroll
    for (int mf = 0; mf < 2; ++mf)
        #pragma unroll
        for (int nb = 0; nb < 2; ++nb) {
            int col = n0 + wn + nb * 8 + tc * 2;
            #pragma unroll
            for (int half = 0; half < 2; ++half) {
                int row = m0 + wm + mf * 16 + g + half * 8;
                float v0 = c[mf][nb][half * 2 + 0];
                float v1 = c[mf][nb][half * 2 + 1];
                if (MODE == 1) {
                    float tw = tvec[row];
                    v0 += bias[col]     + tw * w1last[col];
                    v1 += bias[col + 1] + tw * w1last[col + 1];
                    v0 = (v0 >= 0.f) ? v0 : 0.01f * v0;
                    v1 = (v1 >= 0.f) ? v1 : 0.01f * v1;
                    *(__nv_bfloat162*)&g_h[(size_t)row * HDIM + col] =
                        __floats2bfloat162_rn(v0, v1);
                } else {
                    v0 += bias[col];
                    v1 += bias[col + 1];
                    *(float2*)&g_out[(size_t)row * NOUT + col] = make_float2(v0, v1);
                }
            }
        }
}

// ---------------- loss: telescoped discretised CDF + weighted SE ----------------
// Each thread owns 4 consecutive elements (float4 loads), giving 4 independent
// erf windows for ILP.
__global__ void __launch_bounds__(256) loss_k(const float* __restrict__ x) {
    int b = blockIdx.x;
    int tid = threadIdx.x;
    float invg = g_invg[b], r = g_r[b], w = g_wgt[b];
    int lowt = g_lowt[b];
    int d0 = tid * 4;

    float4 me4 = *(const float4*)&g_out[b * NOUT + d0];
    float4 ls4 = *(const float4*)&g_out[b * NOUT + DDIM + d0];
    float4 mu4 = *(const float4*)&g_mu[b * DDIM + d0];
    float4 xx4 = *(const float4*)&x[b * DDIM + d0];

    const float* me = &me4.x;
    const float* ls = &ls4.x;
    const float* mu = &mu4.x;
    const float* xv = &xx4.x;

    float acc = 0.f;
    #pragma unroll
    for (int j = 0; j < 4; ++j) {
        float mu_x = mu[j] * invg - r * me[j];
        float sx = r * __expf(ls[j]);
        if (lowt) { mu_x = 0.f; sx = 1.f; }
        float inv  = 0.70710678118654752f / sx;
        float base = (-1.0f - mu_x) * inv;
        float step = 0.015625f * inv;
        float center = 64.f * (1.f + mu_x);
        float halfw  = 256.f / inv;
        int klo = (int)ceilf(center - halfw);
        int khi = (int)floorf(center + halfw);
        klo = klo < 1 ? 1 : (klo > 127 ? 127 : klo);
        khi = khi < 0 ? 0 : (khi > 126 ? 126 : khi);
        float S = (float)(126 - khi) - (float)(klo - 1);
        for (int k = klo; k <= khi; ++k) {
            S += erff(fmaf((float)k, step, base));
        }
        float G127 = 0.5f + 0.5f * erff(fmaf(127.f, step, base));
        float pO = 0.9765625f * G127 - 0.015625f * (63.f + 0.5f * S);
        float diff = xv[j] - pO;
        acc = fmaf(w * diff, diff, acc);
    }

    __shared__ float red[256];
    red[tid] = acc;
    __syncthreads();
    #pragma unroll
    for (int s = 128; s > 0; s >>= 1) {
        if (tid < s) red[tid] += red[tid + s];
        __syncthreads();
    }
    if (tid == 0) g_partial[b] = red[0];
}

__global__ void finalize_k(float* __restrict__ out) {
    __shared__ double red[256];
    red[threadIdx.x] = (double)g_partial[threadIdx.x];
    __syncthreads();
    #pragma unroll
    for (int s = 128; s > 0; s >>= 1) {
        if (threadIdx.x < s) red[threadIdx.x] += red[threadIdx.x + s];
        __syncthreads();
    }
    if (threadIdx.x == 0) out[0] = (float)(3.912023005428146 * red[0] / 262144.0);
}

// ---------------- launch --------------------------------------------------------
extern "C" void kernel_launch(void* const* d_in, const int* in_sizes, int n_in,
                              void* d_out, int out_size) {
    const float* x     = (const float*)d_in[0];   // (256,1024)
    const float* t     = (const float*)d_in[1];   // (256,1)
    const float* noise = (const float*)d_in[2];   // (256,1024)
    const float* W1    = (const float*)d_in[3];   // (1025,2048)
    const float* b1    = (const float*)d_in[4];   // (2048,)
    const float* W2    = (const float*)d_in[5];   // (2048,2048)
    const float* b2    = (const float*)d_in[6];   // (2048,)

    size_t smem = NSTAGE * STAGE_BYTES;   // 55296
    cudaFuncSetAttribute(gemm_k<1>, cudaFuncAttributeMaxDynamicSharedMemorySize, (int)smem);
    cudaFuncSetAttribute(gemm_k<2>, cudaFuncAttributeMaxDynamicSharedMemorySize, (int)smem);

    prep_all_k<<<4096, 256>>>(x, noise, t, W1, W2);

    dim3 ggrid(2048 / 64, BROWS / 64);   // (32, 4) = 128 CTAs
    gemm_k<1><<<ggrid, 256, smem>>>(DDIM, b1, t, W1 + (size_t)DDIM * HDIM);
    gemm_k<2><<<ggrid, 256, smem>>>(HDIM, b2, nullptr, nullptr);

    loss_k<<<BROWS, 256>>>(x);
    finalize_k<<<1, 256>>>((float*)d_out);
}

// round 6
// speedup vs baseline: 2.7491x; 1.6652x over previous
#include <cuda_runtime.h>
#include <cuda_bf16.h>
#include <stdint.h>

#define BROWS 256
#define DDIM  1024
#define HDIM  2048
#define NOUT  2048   // 2*D

// ---------------- scratch (__device__ globals; no allocation allowed) ----------
__device__ float          g_mu[BROWS * DDIM];
__device__ __nv_bfloat16  g_mubf[BROWS * DDIM];
__device__ __nv_bfloat16  g_w1bf[DDIM * HDIM];   // [k=1024][n=2048]
__device__ __nv_bfloat16  g_w2bf[HDIM * NOUT];   // [k=2048][n=2048]
__device__ __nv_bfloat16  g_h[BROWS * HDIM];
__device__ float          g_out[BROWS * NOUT];
__device__ float g_invg[BROWS], g_r[BROWS], g_wgt[BROWS];
__device__ int   g_lowt[BROWS];
__device__ float g_partial[BROWS];

// ---------------- PTX helpers ----------------------------------------------------
__device__ __forceinline__ uint32_t cvta_shared_u32(const void* p) {
    uint32_t a;
    asm("{ .reg .u64 t; cvta.to.shared.u64 t, %1; cvt.u32.u64 %0, t; }"
        : "=r"(a) : "l"(p));
    return a;
}
__device__ __forceinline__ void cpa16(uint32_t dst, const void* src) {
    asm volatile("cp.async.cg.shared.global [%0], [%1], 16;\n" :: "r"(dst), "l"(src));
}
__device__ __forceinline__ void ldm_x4(uint32_t* r, uint32_t addr) {
    asm volatile("ldmatrix.sync.aligned.m8n8.x4.shared.b16 {%0,%1,%2,%3}, [%4];\n"
                 : "=r"(r[0]), "=r"(r[1]), "=r"(r[2]), "=r"(r[3]) : "r"(addr));
}
__device__ __forceinline__ void ldm_x4t(uint32_t* r, uint32_t addr) {
    asm volatile("ldmatrix.sync.aligned.m8n8.x4.trans.shared.b16 {%0,%1,%2,%3}, [%4];\n"
                 : "=r"(r[0]), "=r"(r[1]), "=r"(r[2]), "=r"(r[3]) : "r"(addr));
}
__device__ __forceinline__ void mma16816(float* c, const uint32_t* a, const uint32_t* b) {
    asm volatile(
        "mma.sync.aligned.m16n8k16.row.col.f32.bf16.bf16.f32 "
        "{%0,%1,%2,%3}, {%4,%5,%6,%7}, {%8,%9}, {%0,%1,%2,%3};\n"
        : "+f"(c[0]), "+f"(c[1]), "+f"(c[2]), "+f"(c[3])
        : "r"(a[0]), "r"(a[1]), "r"(a[2]), "r"(a[3]), "r"(b[0]), "r"(b[1]));
}

// ---------------- fused prep: mu + row scalars + both weight converts ------------
__global__ void __launch_bounds__(256) prep_all_k(const float* __restrict__ x,
                                                  const float* __restrict__ noise,
                                                  const float* __restrict__ t,
                                                  const float* __restrict__ W1,
                                                  const float* __restrict__ W2) {
    int blk = blockIdx.x;
    if (blk < 1024) {
        int i = blk * 256 + threadIdx.x;      // < 262144
        int b = i >> 10;
        float tv = __ldg(&t[b]);
        float sg = expf(-7.824046010856292f * tv);
        float gamma = 1.0f - sg;
        float mu = gamma * x[i] + gamma * sg * noise[i];
        g_mu[i]   = mu;
        g_mubf[i] = __float2bfloat16(mu);
        if (blk == 0 && threadIdx.x < BROWS) {
            int bb = threadIdx.x;
            float tb = t[bb];
            float s2 = expf(-7.824046010856292f * tb);
            float g2 = 1.0f - s2;
            g_invg[bb] = 1.0f / g2;
            g_r[bb]    = sqrtf(s2 / g2);
            g_wgt[bb]  = 1.0f / s2;
            g_lowt[bb] = (tb < 1e-10f) ? 1 : 0;
        }
        return;
    }
    const float* src;
    __nv_bfloat16* dst;
    int i;
    if (blk < 2048) {                           // W1
        i = (blk - 1024) * 256 + threadIdx.x;
        src = W1; dst = g_w1bf;
    } else {                                    // W2
        i = (blk - 2048) * 256 + threadIdx.x;
        src = W2; dst = g_w2bf;
    }
    float4 v0 = ((const float4*)src)[2 * i];
    float4 v1 = ((const float4*)src)[2 * i + 1];
    __nv_bfloat162 o[4];
    o[0] = __floats2bfloat162_rn(v0.x, v0.y);
    o[1] = __floats2bfloat162_rn(v0.z, v0.w);
    o[2] = __floats2bfloat162_rn(v1.x, v1.y);
    o[3] = __floats2bfloat162_rn(v1.z, v1.w);
    ((uint4*)dst)[i] = *(uint4*)o;
}

// ---------------- GEMM: C(256 x 2048) = A(256 x K) @ B(K x 2048) -----------------
#define PITCH_B 144
#define STAGE_A (64 * PITCH_B)
#define STAGE_BYTES (2 * 64 * PITCH_B)
#define NSTAGE 3

template <int MODE>
__global__ void __launch_bounds__(256) gemm_k(int Kdim,
                                              const float* __restrict__ bias,
                                              const float* __restrict__ tvec,
                                              const float* __restrict__ w1last) {
    extern __shared__ char smem[];
    uint32_t sbase = cvta_shared_u32(smem);

    const __nv_bfloat16* A = (MODE == 1) ? g_mubf : g_h;
    const __nv_bfloat16* B = (MODE == 1) ? g_w1bf : g_w2bf;

    int tid = threadIdx.x, wid = tid >> 5, lane = tid & 31;
    int m0 = blockIdx.y * 64, n0 = blockIdx.x * 64;
    int wm = (wid >> 2) * 32;
    int wn = (wid & 3) * 16;

    float c[2][2][4];
    #pragma unroll
    for (int mf = 0; mf < 2; ++mf)
        #pragma unroll
        for (int nb = 0; nb < 2; ++nb)
            #pragma unroll
            for (int j = 0; j < 4; ++j) c[mf][nb][j] = 0.f;

    int ntiles = Kdim >> 6;

    auto issue = [&](int tt) {
        uint32_t sA = sbase + (uint32_t)(tt % NSTAGE) * STAGE_BYTES;
        uint32_t sB = sA + STAGE_A;
        int k0 = tt << 6;
        #pragma unroll
        for (int i = 0; i < 2; ++i) {
            int id = tid + i * 256;
            int row = id >> 3, c16 = id & 7;
            cpa16(sA + (uint32_t)(row * PITCH_B + c16 * 16),
                  A + (size_t)(m0 + row) * Kdim + k0 + c16 * 8);
        }
        #pragma unroll
        for (int i = 0; i < 2; ++i) {
            int id = tid + i * 256;
            int row = id >> 3, c16 = id & 7;
            cpa16(sB + (uint32_t)(row * PITCH_B + c16 * 16),
                  B + (size_t)(k0 + row) * 2048 + n0 + c16 * 8);
        }
        asm volatile("cp.async.commit_group;\n" ::: "memory");
    };

    issue(0);
    issue(1);

    for (int tt = 0; tt < ntiles; ++tt) {
        asm volatile("cp.async.wait_group 1;\n" ::: "memory");
        __syncthreads();
        if (tt + 2 < ntiles) issue(tt + 2);
        else asm volatile("cp.async.commit_group;\n" ::: "memory");

        uint32_t sA = sbase + (uint32_t)(tt % NSTAGE) * STAGE_BYTES;
        uint32_t sB = sA + STAGE_A;
        #pragma unroll
        for (int ks = 0; ks < 4; ++ks) {
            uint32_t a[2][4], b[4];
            #pragma unroll
            for (int mf = 0; mf < 2; ++mf)
                ldm_x4(a[mf], sA + (uint32_t)((wm + mf * 16 + (lane & 15)) * PITCH_B
                                              + (ks * 16 + ((lane >> 4) << 3)) * 2));
            ldm_x4t(b, sB + (uint32_t)((ks * 16 + (lane & 15)) * PITCH_B
                                       + (wn + ((lane >> 4) << 3)) * 2));
            #pragma unroll
            for (int mf = 0; mf < 2; ++mf) {
                mma16816(c[mf][0], a[mf], &b[0]);
                mma16816(c[mf][1], a[mf], &b[2]);
            }
        }
    }

    // epilogue
    int tc = lane & 3, g = lane >> 2;
    #pragma unroll
    for (int mf = 0; mf < 2; ++mf)
        #pragma unroll
        for (int nb = 0; nb < 2; ++nb) {
            int col = n0 + wn + nb * 8 + tc * 2;
            #pragma unroll
            for (int half = 0; half < 2; ++half) {
                int row = m0 + wm + mf * 16 + g + half * 8;
                float v0 = c[mf][nb][half * 2 + 0];
                float v1 = c[mf][nb][half * 2 + 1];
                if (MODE == 1) {
                    float tw = tvec[row];
                    v0 += bias[col]     + tw * w1last[col];
                    v1 += bias[col + 1] + tw * w1last[col + 1];
                    v0 = (v0 >= 0.f) ? v0 : 0.01f * v0;
                    v1 = (v1 >= 0.f) ? v1 : 0.01f * v1;
                    *(__nv_bfloat162*)&g_h[(size_t)row * HDIM + col] =
                        __floats2bfloat162_rn(v0, v1);
                } else {
                    v0 += bias[col];
                    v1 += bias[col + 1];
                    *(float2*)&g_out[(size_t)row * NOUT + col] = make_float2(v0, v1);
                }
            }
        }
}

// ---------------- loss: Euler-Maclaurin closed form for the bin sum --------------
// S = sum_{k=1..126} erf(base + k*h). For h <= 0.5 use midpoint-rule EM expansion:
//   S = (1/h)[A(b)-A(a)] - (h/24)[f'(b)-f'(a)] + (7h^3/5760)[f'''(b)-f'''(a)]
//   A(x) = x*erf(x) + exp(-x^2)/sqrt(pi); f' = c*exp(-x^2); f''' = c*(4x^2-2)exp(-x^2)
//   a = base+0.5h, b = base+126.5h, c = 2/sqrt(pi).
// For h > 0.5 (narrow sigma, high loss weight) window is <=16 bins: exact loop.
__global__ void __launch_bounds__(256) loss_k(const float* __restrict__ x) {
    int b = blockIdx.x;
    int tid = threadIdx.x;
    float invg = g_invg[b], r = g_r[b], w = g_wgt[b];
    int lowt = g_lowt[b];
    int d0 = tid * 4;

    float4 me4 = *(const float4*)&g_out[b * NOUT + d0];
    float4 ls4 = *(const float4*)&g_out[b * NOUT + DDIM + d0];
    float4 mu4 = *(const float4*)&g_mu[b * DDIM + d0];
    float4 xx4 = *(const float4*)&x[b * DDIM + d0];

    const float* me = &me4.x;
    const float* ls = &ls4.x;
    const float* mu = &mu4.x;
    const float* xv = &xx4.x;

    const float C2RP  = 1.1283791671f;      // 2/sqrt(pi)
    const float IRP   = 0.5641895835f;      // 1/sqrt(pi)
    const float CH24  = C2RP / 24.0f;       // 0.0470157986
    const float CH3   = 7.0f * C2RP / 5760.0f; // 0.0013712942

    float acc = 0.f;
    #pragma unroll
    for (int j = 0; j < 4; ++j) {
        float mu_x = mu[j] * invg - r * me[j];
        float sx = r * __expf(ls[j]);
        if (lowt) { mu_x = 0.f; sx = 1.f; }
        float inv  = 0.70710678118654752f / sx;
        float base = (-1.0f - mu_x) * inv;
        float h    = 0.015625f * inv;

        float S;
        if (h > 0.5f) {
            // exact windowed sum: <= 16 active bins
            float center = 64.f * (1.f + mu_x);
            float halfw  = 256.f / inv;
            int klo = (int)ceilf(center - halfw);
            int khi = (int)floorf(center + halfw);
            klo = klo < 1 ? 1 : (klo > 127 ? 127 : klo);
            khi = khi < 0 ? 0 : (khi > 126 ? 126 : khi);
            S = (float)(126 - khi) - (float)(klo - 1);
            for (int k = klo; k <= khi; ++k)
                S += erff(fmaf((float)k, h, base));
        } else {
            float a  = fmaf(0.5f,   h, base);
            float bq = fmaf(126.5f, h, base);
            float ea = __expf(-a * a);
            float eb = __expf(-bq * bq);
            float efa = erff(a), efb = erff(bq);
            float I = (bq * efb - a * efa) + IRP * (eb - ea);
            float rcp = 90.50966799f * sx;   // 1/h = 64*sqrt(2)*sx
            S = I * rcp
              - (h * CH24) * (eb - ea)
              + (h * h * h * CH3) * (fmaf(4.f * bq, bq, -2.f) * eb
                                     - fmaf(4.f * a, a, -2.f) * ea);
        }

        float G127 = 0.5f + 0.5f * erff(fmaf(127.f, h, base));
        float pO = 0.9765625f * G127 - 0.015625f * (63.f + 0.5f * S);
        float diff = xv[j] - pO;
        acc = fmaf(w * diff, diff, acc);
    }

    __shared__ float red[256];
    red[tid] = acc;
    __syncthreads();
    #pragma unroll
    for (int s = 128; s > 0; s >>= 1) {
        if (tid < s) red[tid] += red[tid + s];
        __syncthreads();
    }
    if (tid == 0) g_partial[b] = red[0];
}

__global__ void finalize_k(float* __restrict__ out) {
    __shared__ double red[256];
    red[threadIdx.x] = (double)g_partial[threadIdx.x];
    __syncthreads();
    #pragma unroll
    for (int s = 128; s > 0; s >>= 1) {
        if (threadIdx.x < s) red[threadIdx.x] += red[threadIdx.x + s];
        __syncthreads();
    }
    if (threadIdx.x == 0) out[0] = (float)(3.912023005428146 * red[0] / 262144.0);
}

// ---------------- launch --------------------------------------------------------
extern "C" void kernel_launch(void* const* d_in, const int* in_sizes, int n_in,
                              void* d_out, int out_size) {
    const float* x     = (const float*)d_in[0];   // (256,1024)
    const float* t     = (const float*)d_in[1];   // (256,1)
    const float* noise = (const float*)d_in[2];   // (256,1024)
    const float* W1    = (const float*)d_in[3];   // (1025,2048)
    const float* b1    = (const float*)d_in[4];   // (2048,)
    const float* W2    = (const float*)d_in[5];   // (2048,2048)
    const float* b2    = (const float*)d_in[6];   // (2048,)

    size_t smem = NSTAGE * STAGE_BYTES;   // 55296
    cudaFuncSetAttribute(gemm_k<1>, cudaFuncAttributeMaxDynamicSharedMemorySize, (int)smem);
    cudaFuncSetAttribute(gemm_k<2>, cudaFuncAttributeMaxDynamicSharedMemorySize, (int)smem);

    prep_all_k<<<4096, 256>>>(x, noise, t, W1, W2);

    dim3 ggrid(2048 / 64, BROWS / 64);   // (32, 4) = 128 CTAs
    gemm_k<1><<<ggrid, 256, smem>>>(DDIM, b1, t, W1 + (size_t)DDIM * HDIM);
    gemm_k<2><<<ggrid, 256, smem>>>(HDIM, b2, nullptr, nullptr);

    loss_k<<<BROWS, 256>>>(x);
    finalize_k<<<1, 256>>>((float*)d_out);
}

// round 7
// speedup vs baseline: 2.7839x; 1.0127x over previous
#include <cuda_runtime.h>
#include <cuda_bf16.h>
#include <stdint.h>

#define BROWS 256
#define DDIM  1024
#define HDIM  2048
#define NOUT  2048   // 2*D

// ---------------- scratch (__device__ globals; no allocation allowed) ----------
__device__ float          g_mu[BROWS * DDIM];
__device__ __nv_bfloat16  g_mubf[BROWS * DDIM];
__device__ __nv_bfloat16  g_w1bf[DDIM * HDIM];   // [k=1024][n=2048]
__device__ __nv_bfloat16  g_w2bf[HDIM * NOUT];   // [k=2048][n=2048]
__device__ __nv_bfloat16  g_h[BROWS * HDIM];
__device__ float          g_out[BROWS * NOUT];    // gemm2 split-K partial 0 (+bias)
__device__ float          g_out2[BROWS * NOUT];   // gemm2 split-K partial 1
__device__ float g_invg[BROWS], g_r[BROWS], g_wgt[BROWS];
__device__ int   g_lowt[BROWS];
__device__ float g_partial[1024];

// ---------------- PTX helpers ----------------------------------------------------
__device__ __forceinline__ uint32_t cvta_shared_u32(const void* p) {
    uint32_t a;
    asm("{ .reg .u64 t; cvta.to.shared.u64 t, %1; cvt.u32.u64 %0, t; }"
        : "=r"(a) : "l"(p));
    return a;
}
__device__ __forceinline__ void cpa16(uint32_t dst, const void* src) {
    asm volatile("cp.async.cg.shared.global [%0], [%1], 16;\n" :: "r"(dst), "l"(src));
}
__device__ __forceinline__ void ldm_x4(uint32_t* r, uint32_t addr) {
    asm volatile("ldmatrix.sync.aligned.m8n8.x4.shared.b16 {%0,%1,%2,%3}, [%4];\n"
                 : "=r"(r[0]), "=r"(r[1]), "=r"(r[2]), "=r"(r[3]) : "r"(addr));
}
__device__ __forceinline__ void ldm_x4t(uint32_t* r, uint32_t addr) {
    asm volatile("ldmatrix.sync.aligned.m8n8.x4.trans.shared.b16 {%0,%1,%2,%3}, [%4];\n"
                 : "=r"(r[0]), "=r"(r[1]), "=r"(r[2]), "=r"(r[3]) : "r"(addr));
}
__device__ __forceinline__ void mma16816(float* c, const uint32_t* a, const uint32_t* b) {
    asm volatile(
        "mma.sync.aligned.m16n8k16.row.col.f32.bf16.bf16.f32 "
        "{%0,%1,%2,%3}, {%4,%5,%6,%7}, {%8,%9}, {%0,%1,%2,%3};\n"
        : "+f"(c[0]), "+f"(c[1]), "+f"(c[2]), "+f"(c[3])
        : "r"(a[0]), "r"(a[1]), "r"(a[2]), "r"(a[3]), "r"(b[0]), "r"(b[1]));
}

// ---------------- fast erf (Abramowitz-Stegun 7.1.26, |err| <= 1.5e-7) ----------
__device__ __forceinline__ float erf_fast_e(float x, float e /* = exp(-x*x) */) {
    float ax = fabsf(x);
    float t = __fdividef(1.0f, fmaf(0.3275911f, ax, 1.0f));
    float p = fmaf(fmaf(fmaf(fmaf(1.061405429f, t, -1.453152027f), t,
                             1.421413741f), t, -0.284496736f), t, 0.254829592f) * t;
    return copysignf(1.0f - p * e, x);
}
__device__ __forceinline__ float erf_fast(float x) {
    return erf_fast_e(x, __expf(-x * x));
}

// ---------------- fused prep: mu + row scalars + both weight converts ------------
__global__ void __launch_bounds__(256) prep_all_k(const float* __restrict__ x,
                                                  const float* __restrict__ noise,
                                                  const float* __restrict__ t,
                                                  const float* __restrict__ W1,
                                                  const float* __restrict__ W2) {
    int blk = blockIdx.x;
    if (blk < 1024) {
        int i = blk * 256 + threadIdx.x;      // < 262144
        int b = i >> 10;
        float tv = __ldg(&t[b]);
        float sg = expf(-7.824046010856292f * tv);
        float gamma = 1.0f - sg;
        float mu = gamma * x[i] + gamma * sg * noise[i];
        g_mu[i]   = mu;
        g_mubf[i] = __float2bfloat16(mu);
        if (blk == 0 && threadIdx.x < BROWS) {
            int bb = threadIdx.x;
            float tb = t[bb];
            float s2 = expf(-7.824046010856292f * tb);
            float g2 = 1.0f - s2;
            g_invg[bb] = 1.0f / g2;
            g_r[bb]    = sqrtf(s2 / g2);
            g_wgt[bb]  = 1.0f / s2;
            g_lowt[bb] = (tb < 1e-10f) ? 1 : 0;
        }
        return;
    }
    const float* src;
    __nv_bfloat16* dst;
    int i;
    if (blk < 2048) {                           // W1
        i = (blk - 1024) * 256 + threadIdx.x;
        src = W1; dst = g_w1bf;
    } else {                                    // W2
        i = (blk - 2048) * 256 + threadIdx.x;
        src = W2; dst = g_w2bf;
    }
    float4 v0 = ((const float4*)src)[2 * i];
    float4 v1 = ((const float4*)src)[2 * i + 1];
    __nv_bfloat162 o[4];
    o[0] = __floats2bfloat162_rn(v0.x, v0.y);
    o[1] = __floats2bfloat162_rn(v0.z, v0.w);
    o[2] = __floats2bfloat162_rn(v1.x, v1.y);
    o[3] = __floats2bfloat162_rn(v1.z, v1.w);
    ((uint4*)dst)[i] = *(uint4*)o;
}

// ---------------- GEMM: BM=32, BN=64, BK=64, 256 thr (8 warps 2x4, tile 16x16) ----
// MODE 1: A=g_mubf (lda 1024), K=1024. Epi: +b1 + t*W1last, leaky -> g_h (bf16)
// MODE 2: A=g_h (lda 2048), split-K: z in {0,1}, Klen=1024 each.
//         z=0 -> g_out (+bias), z=1 -> g_out2 (partial only)
#define BM 32
#define BN 64
#define BK 64
#define PITCH_B 144
#define STAGE_A   (BM * PITCH_B)            // 4608
#define STAGE_BB  (BK * PITCH_B)            // 9216
#define STAGE_BYTES (STAGE_A + STAGE_BB)    // 13824
#define NSTAGE 3

template <int MODE>
__global__ void __launch_bounds__(256) gemm_k(int lda, int Klen,
                                              const float* __restrict__ bias,
                                              const float* __restrict__ tvec,
                                              const float* __restrict__ w1last) {
    extern __shared__ char smem[];
    uint32_t sbase = cvta_shared_u32(smem);

    const __nv_bfloat16* A = (MODE == 1) ? g_mubf : g_h;
    const __nv_bfloat16* B = (MODE == 1) ? g_w1bf : g_w2bf;

    int tid = threadIdx.x, wid = tid >> 5, lane = tid & 31;
    int m0 = blockIdx.y * BM, n0 = blockIdx.x * BN;
    int koff = (MODE == 2) ? blockIdx.z * Klen : 0;
    int wm = (wid >> 2) * 16;      // 0 / 16
    int wn = (wid & 3) * 16;       // 0 / 16 / 32 / 48

    float c[2][4];
    #pragma unroll
    for (int nb = 0; nb < 2; ++nb)
        #pragma unroll
        for (int j = 0; j < 4; ++j) c[nb][j] = 0.f;

    int ntiles = Klen >> 6;

    auto issue = [&](int tt) {
        uint32_t sA = sbase + (uint32_t)(tt % NSTAGE) * STAGE_BYTES;
        uint32_t sB = sA + STAGE_A;
        int k0 = (tt << 6) + koff;
        {   // A: 32 rows x 8 chunks = 256 -> one per thread
            int row = tid >> 3, c16 = tid & 7;
            cpa16(sA + (uint32_t)(row * PITCH_B + c16 * 16),
                  A + (size_t)(m0 + row) * lda + k0 + c16 * 8);
        }
        #pragma unroll
        for (int i = 0; i < 2; ++i) {   // B: 64 x 8 = 512 -> two per thread
            int id = tid + i * 256;
            int row = id >> 3, c16 = id & 7;
            cpa16(sB + (uint32_t)(row * PITCH_B + c16 * 16),
                  B + (size_t)(k0 + row) * 2048 + n0 + c16 * 8);
        }
        asm volatile("cp.async.commit_group;\n" ::: "memory");
    };

    issue(0);
    issue(1);

    for (int tt = 0; tt < ntiles; ++tt) {
        asm volatile("cp.async.wait_group 1;\n" ::: "memory");
        __syncthreads();
        if (tt + 2 < ntiles) issue(tt + 2);
        else asm volatile("cp.async.commit_group;\n" ::: "memory");

        uint32_t sA = sbase + (uint32_t)(tt % NSTAGE) * STAGE_BYTES;
        uint32_t sB = sA + STAGE_A;
        #pragma unroll
        for (int ks = 0; ks < 4; ++ks) {
            uint32_t a[4], b[4];
            ldm_x4(a, sA + (uint32_t)((wm + (lane & 15)) * PITCH_B
                                      + (ks * 16 + ((lane >> 4) << 3)) * 2));
            ldm_x4t(b, sB + (uint32_t)((ks * 16 + (lane & 15)) * PITCH_B
                                       + (wn + ((lane >> 4) << 3)) * 2));
            mma16816(c[0], a, &b[0]);
            mma16816(c[1], a, &b[2]);
        }
    }

    // epilogue
    int tc = lane & 3, g = lane >> 2;
    #pragma unroll
    for (int nb = 0; nb < 2; ++nb) {
        int col = n0 + wn + nb * 8 + tc * 2;
        #pragma unroll
        for (int half = 0; half < 2; ++half) {
            int row = m0 + wm + g + half * 8;
            float v0 = c[nb][half * 2 + 0];
            float v1 = c[nb][half * 2 + 1];
            if (MODE == 1) {
                float tw = tvec[row];
                v0 += bias[col]     + tw * w1last[col];
                v1 += bias[col + 1] + tw * w1last[col + 1];
                v0 = (v0 >= 0.f) ? v0 : 0.01f * v0;
                v1 = (v1 >= 0.f) ? v1 : 0.01f * v1;
                *(__nv_bfloat162*)&g_h[(size_t)row * HDIM + col] =
                    __floats2bfloat162_rn(v0, v1);
            } else {
                float* dst = (blockIdx.z == 0) ? g_out : g_out2;
                if (blockIdx.z == 0) {
                    v0 += bias[col];
                    v1 += bias[col + 1];
                }
                *(float2*)&dst[(size_t)row * NOUT + col] = make_float2(v0, v1);
            }
        }
    }
}

// ---------------- loss: EM closed form + fast erf, 1 elem/thread -----------------
__global__ void __launch_bounds__(256) loss_k(const float* __restrict__ x) {
    int blk = blockIdx.x;            // 1024 blocks
    int tid = threadIdx.x;
    int b = blk >> 2;
    int d = ((blk & 3) << 8) + tid;  // 0..1023
    float invg = g_invg[b], r = g_r[b], w = g_wgt[b];
    int lowt = g_lowt[b];

    float me = g_out[b * NOUT + d]        + g_out2[b * NOUT + d];
    float ls = g_out[b * NOUT + DDIM + d] + g_out2[b * NOUT + DDIM + d];
    float muv = g_mu[b * DDIM + d];
    float xv  = x[b * DDIM + d];

    const float IRP  = 0.5641895835f;          // 1/sqrt(pi)
    const float CH24 = 1.1283791671f / 24.0f;
    const float CH3  = 7.0f * 1.1283791671f / 5760.0f;

    float mu_x = muv * invg - r * me;
    float sx = r * __expf(ls);
    if (lowt) { mu_x = 0.f; sx = 1.f; }
    float inv  = 0.70710678118654752f / sx;
    float base = (-1.0f - mu_x) * inv;
    float h    = 0.015625f * inv;

    float S;
    if (h > 0.5f) {
        // exact windowed sum: <= 16 active bins
        float center = 64.f * (1.f + mu_x);
        float halfw  = 256.f / inv;
        int klo = (int)ceilf(center - halfw);
        int khi = (int)floorf(center + halfw);
        klo = klo < 1 ? 1 : (klo > 127 ? 127 : klo);
        khi = khi < 0 ? 0 : (khi > 126 ? 126 : khi);
        S = (float)(126 - khi) - (float)(klo - 1);
        for (int k = klo; k <= khi; ++k)
            S += erf_fast(fmaf((float)k, h, base));
    } else {
        float a  = fmaf(0.5f,   h, base);
        float bq = fmaf(126.5f, h, base);
        float ea = __expf(-a * a);
        float eb = __expf(-bq * bq);
        float efa = erf_fast_e(a, ea), efb = erf_fast_e(bq, eb);
        float I = (bq * efb - a * efa) + IRP * (eb - ea);
        float rcp = 90.50966799f * sx;   // 1/h
        S = I * rcp
          - (h * CH24) * (eb - ea)
          + (h * h * h * CH3) * (fmaf(4.f * bq, bq, -2.f) * eb
                                 - fmaf(4.f * a, a, -2.f) * ea);
    }

    float G127 = 0.5f + 0.5f * erf_fast(fmaf(127.f, h, base));
    float pO = 0.9765625f * G127 - 0.015625f * (63.f + 0.5f * S);
    float diff = xv - pO;
    float acc = w * diff * diff;

    __shared__ float red[256];
    red[tid] = acc;
    __syncthreads();
    #pragma unroll
    for (int s = 128; s > 0; s >>= 1) {
        if (tid < s) red[tid] += red[tid + s];
        __syncthreads();
    }
    if (tid == 0) g_partial[blk] = red[0];
}

__global__ void finalize_k(float* __restrict__ out) {
    int tid = threadIdx.x;
    __shared__ double red[256];
    double s = 0.0;
    #pragma unroll
    for (int i = 0; i < 4; ++i) s += (double)g_partial[tid + i * 256];
    red[tid] = s;
    __syncthreads();
    #pragma unroll
    for (int st = 128; st > 0; st >>= 1) {
        if (tid < st) red[tid] += red[tid + st];
        __syncthreads();
    }
    if (tid == 0) out[0] = (float)(3.912023005428146 * red[0] / 262144.0);
}

// ---------------- launch --------------------------------------------------------
extern "C" void kernel_launch(void* const* d_in, const int* in_sizes, int n_in,
                              void* d_out, int out_size) {
    const float* x     = (const float*)d_in[0];   // (256,1024)
    const float* t     = (const float*)d_in[1];   // (256,1)
    const float* noise = (const float*)d_in[2];   // (256,1024)
    const float* W1    = (const float*)d_in[3];   // (1025,2048)
    const float* b1    = (const float*)d_in[4];   // (2048,)
    const float* W2    = (const float*)d_in[5];   // (2048,2048)
    const float* b2    = (const float*)d_in[6];   // (2048,)

    size_t smem = NSTAGE * STAGE_BYTES;   // 41472 (< 48KB default)

    prep_all_k<<<4096, 256>>>(x, noise, t, W1, W2);

    dim3 g1(2048 / BN, BROWS / BM);       // (32, 8) = 256 CTAs
    gemm_k<1><<<g1, 256, smem>>>(DDIM, DDIM, b1, t, W1 + (size_t)DDIM * HDIM);

    dim3 g2(2048 / BN, BROWS / BM, 2);    // (32, 8, 2) = 512 CTAs, split-K
    gemm_k<2><<<g2, 256, smem>>>(HDIM, 1024, b2, nullptr, nullptr);

    loss_k<<<1024, 256>>>(x);
    finalize_k<<<1, 256>>>((float*)d_out);
}